// round 4
// baseline (speedup 1.0000x reference)
#include <cuda_runtime.h>

typedef unsigned long long u64;

#define NK 16
#define TW 520            // tile row stride in floats; gx stored at idx gx+4

__device__ __forceinline__ u64 pack2(float lo, float hi) {
    u64 r; asm("mov.b64 %0, {%1, %2};" : "=l"(r) : "f"(lo), "f"(hi)); return r;
}
__device__ __forceinline__ void unpack2(u64 v, float& lo, float& hi) {
    asm("mov.b64 {%0, %1}, %2;" : "=f"(lo), "=f"(hi) : "l"(v));
}
__device__ __forceinline__ u64 fma2(u64 a, u64 b, u64 c) {
    u64 d; asm("fma.rn.f32x2 %0, %1, %2, %3;" : "=l"(d) : "l"(a), "l"(b), "l"(c)); return d;
}
__device__ __forceinline__ u64 add2_(u64 a, u64 b) {
    u64 d; asm("add.rn.f32x2 %0, %1, %2;" : "=l"(d) : "l"(a), "l"(b)); return d;
}
// tanh on both halves IN PLACE: same pair register in and out, so ptxas can
// allocate lo/hi as the pair's own halves and drop the pack/unpack MOVs.
__device__ __forceinline__ void tanh2_ip(u64& v) {
    asm("{\n\t"
        ".reg .f32 lo, hi;\n\t"
        "mov.b64 {lo, hi}, %0;\n\t"
        "tanh.approx.f32 lo, lo;\n\t"
        "tanh.approx.f32 hi, hi;\n\t"
        "mov.b64 %0, {lo, hi};\n\t"
        "}" : "+l"(v));
}
__device__ __forceinline__ float addsat_(float a, float b) {
    float r; asm("add.rn.sat.f32 %0, %1, %2;" : "=f"(r) : "f"(a), "f"(b)); return r;
}

// Grid: (128 tiles of 4 rows, 16 batch). Block: (128, 2) = 256 threads.
// Each thread: 2 rows x 4 cols = 8 pixels (4 f32x2 pairs).
__global__ void __launch_bounds__(256, 3)
ca_kernel(const float* __restrict__ x, const float* __restrict__ w,
          const float* __restrict__ react, const float* __restrict__ prod,
          float* __restrict__ out)
{
    __shared__ __align__(16) float tile[6][TW];   // rows y0-1 .. y0+4
    __shared__ u64 wk[NK][9];    // 5*conv_weight, duplicated (v,v)
    __shared__ u64 mrk[NK];      // (-5*reactant, -5*reactant)
    __shared__ u64 pk[NK];       // (0.5*product, 0.5*product)
    __shared__ float psumh;      // 0.5 * sum(products)

    const int b   = blockIdx.y;
    const int y0  = blockIdx.x * 4;
    const int tx  = threadIdx.x;            // 0..127
    const int ty  = threadIdx.y;            // 0..1
    const int tid = ty * 128 + tx;

    // ---- stage constants (packed/duplicated for f32x2 operands) ----
    if (tid < NK * 9) {
        int k = tid / 9, t = tid - k * 9;
        float v = 5.0f * w[k * 9 + t];            // fold GAIN/2 into weights
        wk[k][t] = pack2(v, v);
    } else if (tid < NK * 10) {
        int k = tid - NK * 9;
        float v = -5.0f * react[k];               // z = 5N - 5r
        mrk[k] = pack2(v, v);
    } else if (tid < NK * 11) {
        int k = tid - NK * 10;
        float v = 0.5f * prod[k];
        pk[k] = pack2(v, v);
    } else if (tid == NK * 11) {
        float s = 0.0f;
        #pragma unroll
        for (int k = 0; k < NK; k++) s += prod[k];
        psumh = 0.5f * s;
    }

    // ---- zero halo column regions: float4 at idx 0 and idx 516, all 6 rows ----
    if (tid < 12) {
        int r = tid >> 1;
        int c = (tid & 1) ? 516 : 0;
        *(float4*)&tile[r][c] = make_float4(0.f, 0.f, 0.f, 0.f);
    }

    // ---- interior tile load: 6 rows x 128 float4 = 768 / 256 thr = 3 each ----
    const float* xb = x + (size_t)b * (512 * 512);
    #pragma unroll
    for (int it = 0; it < 3; it++) {
        int i  = tid + it * 256;
        int r  = i >> 7;                  // 0..5
        int c  = (i & 127) << 2;          // 0,4,..,508
        int gy = y0 - 1 + r;
        float4 v = make_float4(0.f, 0.f, 0.f, 0.f);
        if ((unsigned)gy < 512u)
            v = *(const float4*)(xb + (size_t)gy * 512 + c);
        *(float4*)&tile[r][c + 4] = v;
    }
    __syncthreads();

    // ---- register neighborhood: 4 tile rows x 5 shifted float2 windows ----
    // v[j] = trow[4tx+3+j] (gx-1 .. gx+4, gx = 4*tx).
    // Windows 1,3 are 8B-aligned -> native LDS.64, zero MOV.
    // Windows 0,2,4 packed from already-loaded halves (2 MOV each).
    u64 nb[4][5];
    #pragma unroll
    for (int q = 0; q < 4; q++) {
        const float* trow = tile[2 * ty + q];
        float4 a  = *(const float4*)(trow + 4 * tx);          // a.w = v0 (gx-1)
        u64 w1    = *(const u64*)(trow + 4 * tx + 4);         // (v1,v2) = (gx, gx+1)
        u64 w3    = *(const u64*)(trow + 4 * tx + 6);         // (v3,v4)
        float4 bq = *(const float4*)(trow + 4 * tx + 8);      // bq.x = v5 (gx+4)
        float v1, v2, v3, v4;
        unpack2(w1, v1, v2);
        unpack2(w3, v3, v4);
        nb[q][0] = pack2(a.w, v1);
        nb[q][1] = w1;
        nb[q][2] = pack2(v2, v3);
        nb[q][3] = w3;
        nb[q][4] = pack2(v4, bq.x);
    }

    // accumulators: [row][pair]
    u64 aP00 = 0ull, aP01 = 0ull, aP10 = 0ull, aP11 = 0ull;  // sum(t_k * 0.5 p_k)
    u64 aS00 = 0ull, aS01 = 0ull, aS10 = 0ull, aS11 = 0ull;  // sum(t_k)

    #pragma unroll
    for (int k = 0; k < NK; k++) {
        const u64 mk = mrk[k];
        // conv chains init with bias -> produce z = 5N - 5r directly
        u64 wv  = wk[k][0];
        u64 z00 = fma2(wv, nb[0][0], mk);
        u64 z01 = fma2(wv, nb[0][2], mk);
        u64 z10 = fma2(wv, nb[1][0], mk);
        u64 z11 = fma2(wv, nb[1][2], mk);
        #pragma unroll
        for (int t = 1; t < 9; t++) {
            const int r = t / 3, c = t - 3 * r;
            wv  = wk[k][t];
            z00 = fma2(wv, nb[r][c],         z00);
            z01 = fma2(wv, nb[r][c + 2],     z01);
            z10 = fma2(wv, nb[r + 1][c],     z10);
            z11 = fma2(wv, nb[r + 1][c + 2], z11);
        }
        tanh2_ip(z00); tanh2_ip(z01); tanh2_ip(z10); tanh2_ip(z11);
        const u64 pkk = pk[k];
        aP00 = fma2(z00, pkk, aP00);  aS00 = add2_(z00, aS00);
        aP01 = fma2(z01, pkk, aP01);  aS01 = add2_(z01, aS01);
        aP10 = fma2(z10, pkk, aP10);  aS10 = add2_(z10, aS10);
        aP11 = fma2(z11, pkk, aP11);  aS11 = add2_(z11, aS11);
    }

    // ---- epilogue: out = sat( 0.5*sum(p) + aP + x*(-0.5*aS - 7) ) ----
    const float ps = psumh;
    const u64 MH2 = pack2(-0.5f, -0.5f);
    const u64 M72 = pack2(-7.0f, -7.0f);

    const int gy0 = y0 + 2 * ty;
    float* ob = out + (size_t)b * (512 * 512) + (size_t)gy0 * 512 + 4 * tx;

    {   // row 0: centers nb[1][1], nb[1][3]
        u64 o0 = fma2(nb[1][1], fma2(aS00, MH2, M72), aP00);
        u64 o1 = fma2(nb[1][3], fma2(aS01, MH2, M72), aP01);
        float r0, r1, r2, r3;
        unpack2(o0, r0, r1); unpack2(o1, r2, r3);
        *(float4*)ob = make_float4(addsat_(r0, ps), addsat_(r1, ps),
                                   addsat_(r2, ps), addsat_(r3, ps));
    }
    {   // row 1: centers nb[2][1], nb[2][3]
        u64 o0 = fma2(nb[2][1], fma2(aS10, MH2, M72), aP10);
        u64 o1 = fma2(nb[2][3], fma2(aS11, MH2, M72), aP11);
        float r0, r1, r2, r3;
        unpack2(o0, r0, r1); unpack2(o1, r2, r3);
        *(float4*)(ob + 512) = make_float4(addsat_(r0, ps), addsat_(r1, ps),
                                           addsat_(r2, ps), addsat_(r3, ps));
    }
}

extern "C" void kernel_launch(void* const* d_in, const int* in_sizes, int n_in,
                              void* d_out, int out_size) {
    const float* x = (const float*)d_in[0];
    const float* w = (const float*)d_in[1];
    const float* r = (const float*)d_in[2];
    const float* p = (const float*)d_in[3];
    dim3 grid(128, 16);   // 512/4 row tiles, 16 batch images
    dim3 block(128, 2);
    ca_kernel<<<grid, block>>>(x, w, r, p, (float*)d_out);
}

// round 5
// speedup vs baseline: 1.0059x; 1.0059x over previous
#include <cuda_runtime.h>

typedef unsigned long long u64;

#define NK 16
#define TW 136           // tile row stride in floats (col c stores gcol = bx*128 + c - 4)

__device__ __forceinline__ u64 pack2(float lo, float hi) {
    u64 r; asm("mov.b64 %0, {%1, %2};" : "=l"(r) : "f"(lo), "f"(hi)); return r;
}
__device__ __forceinline__ void unpack2(u64 v, float& lo, float& hi) {
    asm("mov.b64 {%0, %1}, %2;" : "=f"(lo), "=f"(hi) : "l"(v));
}
__device__ __forceinline__ u64 fma2(u64 a, u64 b, u64 c) {
    u64 d; asm("fma.rn.f32x2 %0, %1, %2, %3;" : "=l"(d) : "l"(a), "l"(b), "l"(c)); return d;
}
__device__ __forceinline__ u64 add2_(u64 a, u64 b) {
    u64 d; asm("add.rn.f32x2 %0, %1, %2;" : "=l"(d) : "l"(a), "l"(b)); return d;
}
__device__ __forceinline__ void tanh2_ip(u64& v) {
    asm("{\n\t"
        ".reg .f32 lo, hi;\n\t"
        "mov.b64 {lo, hi}, %0;\n\t"
        "tanh.approx.f32 lo, lo;\n\t"
        "tanh.approx.f32 hi, hi;\n\t"
        "mov.b64 %0, {lo, hi};\n\t"
        "}" : "+l"(v));
}
__device__ __forceinline__ float addsat_(float a, float b) {
    float r; asm("add.rn.sat.f32 %0, %1, %2;" : "=f"(r) : "f"(a), "f"(b)); return r;
}

// Grid: (4 col-tiles, 64 row-tiles, 16 batch). Block (64,4) = 256 thr.
// Block covers 8 rows x 128 cols. Thread: 2 rows x 2 cols = 4 px (2 pairs).
__global__ void __launch_bounds__(256, 4)
ca_kernel(const float* __restrict__ x, const float* __restrict__ w,
          const float* __restrict__ react, const float* __restrict__ prod,
          float* __restrict__ out)
{
    // per-k constant record: [w0..w8 (x5, dup), mk=(-5r,dup), pk=(0.5p,dup), pad]
    __shared__ __align__(16) u64 crec[NK][12];
    __shared__ __align__(16) float tile[10][TW];   // rows gy0-1 .. gy0+8
    __shared__ float psumh;

    const int bx  = blockIdx.x;
    const int by  = blockIdx.y;
    const int b   = blockIdx.z;
    const int tx  = threadIdx.x;            // 0..63 -> col pair 2*tx
    const int ty  = threadIdx.y;            // 0..3  -> rows 2*ty, 2*ty+1
    const int tid = ty * 64 + tx;

    // ---- stage per-k constant records ----
    if (tid < NK * 12) {
        int k = tid / 12, j = tid - k * 12;
        u64 v = 0ull;
        if (j < 9) {
            float t = 5.0f * w[k * 9 + j];
            v = pack2(t, t);
        } else if (j == 9) {
            float t = -5.0f * react[k];
            v = pack2(t, t);
        } else if (j == 10) {
            float t = 0.5f * prod[k];
            v = pack2(t, t);
        }
        crec[k][j] = v;
    } else if (tid == NK * 12) {
        float s = 0.0f;
        #pragma unroll
        for (int k = 0; k < NK; k++) s += prod[k];
        psumh = 0.5f * s;
    }

    // ---- tile load: 10 rows x 34 float4 = 340 loads ----
    // tile[r][c] stores gcol = bx*128 + c - 4, row gy = by*8 + r - 1.
    const float* xb = x + (size_t)b * (512 * 512);
    #pragma unroll
    for (int it = 0; it < 2; it++) {
        int i = tid + it * 256;
        if (i < 340) {
            int r   = i / 34;
            int c4  = i - r * 34;
            int gy  = by * 8 + r - 1;
            int gc0 = bx * 128 + c4 * 4 - 4;
            float4 v = make_float4(0.f, 0.f, 0.f, 0.f);
            if ((unsigned)gy < 512u && (unsigned)gc0 < 512u)
                v = *(const float4*)(xb + (size_t)gy * 512 + gc0);
            *(float4*)&tile[r][c4 * 4] = v;
        }
    }
    __syncthreads();

    // ---- register neighborhood: 4 tile rows x 3 windows ----
    // thread gcols (2tx, 2tx+1); taps need gcols 2tx-1..2tx+2 = tile cols 2tx+3..2tx+6.
    // Per row: L=(2tx+2,2tx+3), M=(2tx+4,2tx+5)=w1, R=(2tx+6,2tx+7). All 8B-aligned.
    u64 nb[4][3];
    #pragma unroll
    for (int q = 0; q < 4; q++) {
        const float* trow = tile[2 * ty + q];
        u64 L = *(const u64*)(trow + 2 * tx + 2);
        u64 M = *(const u64*)(trow + 2 * tx + 4);
        u64 R = *(const u64*)(trow + 2 * tx + 6);
        float l0, l1, m0, m1, r0, r1;
        unpack2(L, l0, l1);
        unpack2(M, m0, m1);
        unpack2(R, r0, r1);
        nb[q][0] = pack2(l1, m0);   // (v0, v1)
        nb[q][1] = M;               // (v1, v2)
        nb[q][2] = pack2(m1, r0);   // (v2, v3)
    }

    u64 aP0 = 0ull, aP1 = 0ull;   // sum(t_k * 0.5 p_k), rows 0/1
    u64 aS0 = 0ull, aS1 = 0ull;   // sum(t_k)

    #pragma unroll
    for (int k = 0; k < NK; k++) {
        // 6x LDS.128: w0..w8, mk, pk, pad
        ulonglong2 q0 = *(const ulonglong2*)&crec[k][0];
        ulonglong2 q1 = *(const ulonglong2*)&crec[k][2];
        ulonglong2 q2 = *(const ulonglong2*)&crec[k][4];
        ulonglong2 q3 = *(const ulonglong2*)&crec[k][6];
        ulonglong2 q4 = *(const ulonglong2*)&crec[k][8];   // w8, mk
        ulonglong2 q5 = *(const ulonglong2*)&crec[k][10];  // pk, pad
        const u64 mk = q4.y, pkk = q5.x;

        // conv chains init with bias -> z = 5N - 5r directly
        u64 z0 = fma2(q0.x, nb[0][0], mk);     // row 0 output (tile rows 0..2)
        u64 z1 = fma2(q0.x, nb[1][0], mk);     // row 1 output (tile rows 1..3)
        z0 = fma2(q0.y, nb[0][1], z0);  z1 = fma2(q0.y, nb[1][1], z1);
        z0 = fma2(q1.x, nb[0][2], z0);  z1 = fma2(q1.x, nb[1][2], z1);
        z0 = fma2(q1.y, nb[1][0], z0);  z1 = fma2(q1.y, nb[2][0], z1);
        z0 = fma2(q2.x, nb[1][1], z0);  z1 = fma2(q2.x, nb[2][1], z1);
        z0 = fma2(q2.y, nb[1][2], z0);  z1 = fma2(q2.y, nb[2][2], z1);
        z0 = fma2(q3.x, nb[2][0], z0);  z1 = fma2(q3.x, nb[3][0], z1);
        z0 = fma2(q3.y, nb[2][1], z0);  z1 = fma2(q3.y, nb[3][1], z1);
        z0 = fma2(q4.x, nb[2][2], z0);  z1 = fma2(q4.x, nb[3][2], z1);

        tanh2_ip(z0);
        tanh2_ip(z1);

        aP0 = fma2(z0, pkk, aP0);  aS0 = add2_(z0, aS0);
        aP1 = fma2(z1, pkk, aP1);  aS1 = add2_(z1, aS1);
    }

    // ---- epilogue: out = sat( 0.5*sum(p) + aP + x*(-0.5*aS - 7) ) ----
    const float ps = psumh;
    const u64 MH2 = pack2(-0.5f, -0.5f);
    const u64 M72 = pack2(-7.0f, -7.0f);

    const int gy0 = by * 8 + 2 * ty;
    float* ob = out + (size_t)b * (512 * 512) + (size_t)gy0 * 512 + bx * 128 + 2 * tx;

    u64 o0 = fma2(nb[1][1], fma2(aS0, MH2, M72), aP0);   // centers row 0 = M pair
    u64 o1 = fma2(nb[2][1], fma2(aS1, MH2, M72), aP1);   // centers row 1
    float a0, a1, b0, b1;
    unpack2(o0, a0, a1);
    unpack2(o1, b0, b1);
    *(float2*)ob         = make_float2(addsat_(a0, ps), addsat_(a1, ps));
    *(float2*)(ob + 512) = make_float2(addsat_(b0, ps), addsat_(b1, ps));
}

extern "C" void kernel_launch(void* const* d_in, const int* in_sizes, int n_in,
                              void* d_out, int out_size) {
    const float* x = (const float*)d_in[0];
    const float* w = (const float*)d_in[1];
    const float* r = (const float*)d_in[2];
    const float* p = (const float*)d_in[3];
    dim3 grid(4, 64, 16);   // 4 col-tiles x 64 row-tiles x 16 batch
    dim3 block(64, 4);
    ca_kernel<<<grid, block>>>(x, w, r, p, (float*)d_out);
}

// round 6
// speedup vs baseline: 1.3157x; 1.3080x over previous
#include <cuda_runtime.h>

typedef unsigned long long u64;

#define NK 16
#define TW 136           // tile row stride in floats (col c stores gcol = bx*128 + c - 4)

struct CB {
    u64 crec[NK][12];    // [w0..w8 (x5, dup), mk=(-5r,dup), pk=(0.5p,dup), pad]
    float psumh;         // 0.5 * sum(products)
    float pad;
};

__device__   CB g_cb;    // written by setup kernel
__constant__ CB c_cb;    // main kernel reads (uniform const port, off the smem crossbar)

__device__ __forceinline__ u64 pack2(float lo, float hi) {
    u64 r; asm("mov.b64 %0, {%1, %2};" : "=l"(r) : "f"(lo), "f"(hi)); return r;
}
__device__ __forceinline__ void unpack2(u64 v, float& lo, float& hi) {
    asm("mov.b64 {%0, %1}, %2;" : "=f"(lo), "=f"(hi) : "l"(v));
}
__device__ __forceinline__ u64 fma2(u64 a, u64 b, u64 c) {
    u64 d; asm("fma.rn.f32x2 %0, %1, %2, %3;" : "=l"(d) : "l"(a), "l"(b), "l"(c)); return d;
}
__device__ __forceinline__ u64 add2_(u64 a, u64 b) {
    u64 d; asm("add.rn.f32x2 %0, %1, %2;" : "=l"(d) : "l"(a), "l"(b)); return d;
}
__device__ __forceinline__ void tanh2_ip(u64& v) {
    asm("{\n\t"
        ".reg .f32 lo, hi;\n\t"
        "mov.b64 {lo, hi}, %0;\n\t"
        "tanh.approx.f32 lo, lo;\n\t"
        "tanh.approx.f32 hi, hi;\n\t"
        "mov.b64 %0, {lo, hi};\n\t"
        "}" : "+l"(v));
}
__device__ __forceinline__ float addsat_(float a, float b) {
    float r; asm("add.rn.sat.f32 %0, %1, %2;" : "=f"(r) : "f"(a), "f"(b)); return r;
}

// Setup: transform raw params into the packed constant record (1 block, 256 thr).
__global__ void setup_kernel(const float* __restrict__ w,
                             const float* __restrict__ react,
                             const float* __restrict__ prod)
{
    int tid = threadIdx.x;
    if (tid < NK * 12) {
        int k = tid / 12, j = tid - k * 12;
        u64 v = 0ull;
        if (j < 9) {
            float t = 5.0f * w[k * 9 + j];       // fold GAIN/2 into weights
            v = pack2(t, t);
        } else if (j == 9) {
            float t = -5.0f * react[k];          // z = 5N - 5r
            v = pack2(t, t);
        } else if (j == 10) {
            float t = 0.5f * prod[k];
            v = pack2(t, t);
        }
        g_cb.crec[k][j] = v;
    } else if (tid == NK * 12) {
        float s = 0.0f;
        #pragma unroll
        for (int k = 0; k < NK; k++) s += prod[k];
        g_cb.psumh = 0.5f * s;
        g_cb.pad = 0.0f;
    }
}

// Grid: (4 col-tiles, 64 row-tiles, 16 batch). Block (64,4) = 256 thr.
// Block covers 8 rows x 128 cols. Thread: 2 rows x 2 cols = 4 px (2 pairs).
__global__ void __launch_bounds__(256, 4)
ca_kernel(const float* __restrict__ x, float* __restrict__ out)
{
    __shared__ __align__(16) float tile[10][TW];   // rows gy0-1 .. gy0+8

    const int bx  = blockIdx.x;
    const int by  = blockIdx.y;
    const int b   = blockIdx.z;
    const int tx  = threadIdx.x;            // 0..63 -> col pair 2*tx
    const int ty  = threadIdx.y;            // 0..3  -> rows 2*ty, 2*ty+1
    const int tid = ty * 64 + tx;

    // ---- tile load: 10 rows x 34 float4 = 340 loads ----
    // tile[r][c] stores gcol = bx*128 + c - 4, row gy = by*8 + r - 1.
    const float* xb = x + (size_t)b * (512 * 512);
    #pragma unroll
    for (int it = 0; it < 2; it++) {
        int i = tid + it * 256;
        if (i < 340) {
            int r   = i / 34;
            int c4  = i - r * 34;
            int gy  = by * 8 + r - 1;
            int gc0 = bx * 128 + c4 * 4 - 4;
            float4 v = make_float4(0.f, 0.f, 0.f, 0.f);
            if ((unsigned)gy < 512u && (unsigned)gc0 < 512u)
                v = *(const float4*)(xb + (size_t)gy * 512 + gc0);
            *(float4*)&tile[r][c4 * 4] = v;
        }
    }
    __syncthreads();

    // ---- register neighborhood: 4 tile rows x 3 windows (all LDS.64-aligned) ----
    u64 nb[4][3];
    #pragma unroll
    for (int q = 0; q < 4; q++) {
        const float* trow = tile[2 * ty + q];
        u64 L = *(const u64*)(trow + 2 * tx + 2);
        u64 M = *(const u64*)(trow + 2 * tx + 4);
        u64 R = *(const u64*)(trow + 2 * tx + 6);
        float l0, l1, m0, m1, r0, r1;
        unpack2(L, l0, l1);
        unpack2(M, m0, m1);
        unpack2(R, r0, r1);
        nb[q][0] = pack2(l1, m0);   // (v0, v1)
        nb[q][1] = M;               // (v1, v2)
        nb[q][2] = pack2(m1, r0);   // (v2, v3)
    }

    u64 aP0 = 0ull, aP1 = 0ull;   // sum(t_k * 0.5 p_k), rows 0/1
    u64 aS0 = 0ull, aS1 = 0ull;   // sum(t_k)

    #pragma unroll
    for (int k = 0; k < NK; k++) {
        const u64* cr = c_cb.crec[k];    // uniform const loads (ULDC), no smem traffic
        const u64 mk  = cr[9];
        const u64 pkk = cr[10];

        // conv chains init with bias -> z = 5N - 5r directly
        u64 z0 = fma2(cr[0], nb[0][0], mk);     // row 0 (tile rows 0..2)
        u64 z1 = fma2(cr[0], nb[1][0], mk);     // row 1 (tile rows 1..3)
        z0 = fma2(cr[1], nb[0][1], z0);  z1 = fma2(cr[1], nb[1][1], z1);
        z0 = fma2(cr[2], nb[0][2], z0);  z1 = fma2(cr[2], nb[1][2], z1);
        z0 = fma2(cr[3], nb[1][0], z0);  z1 = fma2(cr[3], nb[2][0], z1);
        z0 = fma2(cr[4], nb[1][1], z0);  z1 = fma2(cr[4], nb[2][1], z1);
        z0 = fma2(cr[5], nb[1][2], z0);  z1 = fma2(cr[5], nb[2][2], z1);
        z0 = fma2(cr[6], nb[2][0], z0);  z1 = fma2(cr[6], nb[3][0], z1);
        z0 = fma2(cr[7], nb[2][1], z0);  z1 = fma2(cr[7], nb[3][1], z1);
        z0 = fma2(cr[8], nb[2][2], z0);  z1 = fma2(cr[8], nb[3][2], z1);

        tanh2_ip(z0);
        tanh2_ip(z1);

        aP0 = fma2(z0, pkk, aP0);  aS0 = add2_(z0, aS0);
        aP1 = fma2(z1, pkk, aP1);  aS1 = add2_(z1, aS1);
    }

    // ---- epilogue: out = sat( 0.5*sum(p) + aP + x*(-0.5*aS - 7) ) ----
    const float ps = c_cb.psumh;
    const u64 MH2 = pack2(-0.5f, -0.5f);
    const u64 M72 = pack2(-7.0f, -7.0f);

    const int gy0 = by * 8 + 2 * ty;
    float* ob = out + (size_t)b * (512 * 512) + (size_t)gy0 * 512 + bx * 128 + 2 * tx;

    u64 o0 = fma2(nb[1][1], fma2(aS0, MH2, M72), aP0);   // centers row 0
    u64 o1 = fma2(nb[2][1], fma2(aS1, MH2, M72), aP1);   // centers row 1
    float a0, a1, b0, b1;
    unpack2(o0, a0, a1);
    unpack2(o1, b0, b1);
    *(float2*)ob         = make_float2(addsat_(a0, ps), addsat_(a1, ps));
    *(float2*)(ob + 512) = make_float2(addsat_(b0, ps), addsat_(b1, ps));
}

extern "C" void kernel_launch(void* const* d_in, const int* in_sizes, int n_in,
                              void* d_out, int out_size) {
    const float* x = (const float*)d_in[0];
    const float* w = (const float*)d_in[1];
    const float* r = (const float*)d_in[2];
    const float* p = (const float*)d_in[3];

    // 1) compute transformed constants into g_cb (device global)
    setup_kernel<<<1, 256>>>(w, r, p);

    // 2) D2D async copy into __constant__ (graph-capturable memcpy node)
    void* gsym = nullptr;
    cudaGetSymbolAddress(&gsym, g_cb);
    cudaMemcpyToSymbolAsync(c_cb, gsym, sizeof(CB), 0, cudaMemcpyDeviceToDevice, 0);

    // 3) main kernel
    dim3 grid(4, 64, 16);   // 4 col-tiles x 64 row-tiles x 16 batch
    dim3 block(64, 4);
    ca_kernel<<<grid, block>>>(x, (float*)d_out);
}